// round 16
// baseline (speedup 1.0000x reference)
#include <cuda_runtime.h>
#include <cuda_bf16.h>
#include <cstdint>

#define NN   100000
#define FIN  256
#define HID  128
#define NC   47
#define NCP  48
#define EMAX 2000000
#define NB   ((NN + 255) / 256)

// ---------------- scratch (device globals) ----------------------------------
__device__ float g_xw [(size_t)NN * HID];
__device__ __nv_bfloat16 g_hhi[(size_t)NN * HID];
__device__ __nv_bfloat16 g_hlo[(size_t)NN * HID];
__device__ float g_hw [(size_t)NN * NCP];
__device__ float g_dinv[NN];
__device__ int   g_cnt [NN];
__device__ int   g_off [NN];
__device__ int   g_tick[EMAX];
__device__ __align__(16) int2 g_csr2[EMAX];     // (src, bits(dinv[src]))
__device__ int   g_total;
__device__ __nv_bfloat16 g_w1t_hi[HID * FIN];
__device__ __nv_bfloat16 g_w1t_lo[HID * FIN];
__device__ __nv_bfloat16 g_w2t_hi[NCP * HID];
__device__ __nv_bfloat16 g_w2t_lo[NCP * HID];

static cudaStream_t g_s1;
static cudaEvent_t  g_evA, g_evB;
static struct StreamInit {
    StreamInit() {
        cudaStreamCreateWithFlags(&g_s1, cudaStreamNonBlocking);
        cudaEventCreateWithFlags(&g_evA, cudaEventDisableTiming);
        cudaEventCreateWithFlags(&g_evB, cudaEventDisableTiming);
    }
} g_streamInit;

typedef unsigned long long ull;

__device__ __forceinline__ void mma_bf16(float *c, const uint32_t *a, const uint32_t *b) {
    asm("mma.sync.aligned.m16n8k16.row.col.f32.bf16.bf16.f32 "
        "{%0,%1,%2,%3}, {%4,%5,%6,%7}, {%8,%9}, {%0,%1,%2,%3};"
        : "+f"(c[0]), "+f"(c[1]), "+f"(c[2]), "+f"(c[3])
        : "r"(a[0]), "r"(a[1]), "r"(a[2]), "r"(a[3]), "r"(b[0]), "r"(b[1]));
}
__device__ __forceinline__ uint32_t bf16x2_of(float f0, float f1) {
    __nv_bfloat162 h = __floats2bfloat162_rn(f0, f1);
    return *reinterpret_cast<uint32_t *>(&h);
}
__device__ __forceinline__ uint32_t smem_u32(const void *p) {
    uint32_t a;
    asm("{ .reg .u64 t; cvta.to.shared.u64 t, %1; cvt.u32.u64 %0, t; }" : "=r"(a) : "l"(p));
    return a;
}
__device__ __forceinline__ void ldm_x4(uint32_t *r, uint32_t addr) {
    asm volatile("ldmatrix.sync.aligned.m8n8.x4.shared.b16 {%0,%1,%2,%3}, [%4];"
                 : "=r"(r[0]), "=r"(r[1]), "=r"(r[2]), "=r"(r[3]) : "r"(addr));
}
__device__ __forceinline__ void ldm_x2(uint32_t *r, uint32_t addr) {
    asm volatile("ldmatrix.sync.aligned.m8n8.x2.shared.b16 {%0,%1}, [%2];"
                 : "=r"(r[0]), "=r"(r[1]) : "r"(addr));
}
__device__ __forceinline__ void cp16(uint32_t dst, const void *src) {
    asm volatile("cp.async.ca.shared.global [%0], [%1], 16;" :: "r"(dst), "l"(src));
}
#define CP_COMMIT() asm volatile("cp.async.commit_group;")
#define CP_WAIT0()  asm volatile("cp.async.wait_group 0;" ::: "memory")

// ---------------- CSR build (ticket trick + paired payload) ------------------
__global__ void k_zero_cnt() {
    int i = blockIdx.x * blockDim.x + threadIdx.x;
    if (i < NN) g_cnt[i] = 0;
    if (blockIdx.x == 0 && threadIdx.x == 0) g_total = 0;
}
__global__ void k_hist(const int *__restrict__ dst, int E) {
    int i = blockIdx.x * blockDim.x + threadIdx.x;
    if (i < E) g_tick[i] = atomicAdd(&g_cnt[dst[i]], 1);
}
__global__ void k_scan_atomic() {           // even-padded offsets
    __shared__ int sh[256];
    __shared__ int base;
    int t = threadIdx.x;
    int i = blockIdx.x * 256 + t;
    int v = (i < NN) ? g_cnt[i] : 0;
    int pad = (v + 1) & ~1;
    sh[t] = pad;
    __syncthreads();
#pragma unroll
    for (int o = 1; o < 256; o <<= 1) {
        int u = (t >= o) ? sh[t - o] : 0;
        __syncthreads();
        sh[t] += u;
        __syncthreads();
    }
    int incl = sh[t];
    if (t == 255) base = atomicAdd(&g_total, incl);
    __syncthreads();
    if (i < NN) {
        g_off[i] = base + incl - pad;       // even
        g_dinv[i] = rsqrtf((float)(v + 1));
    }
}
__global__ void k_fill(const int *__restrict__ src, const int *__restrict__ dst, int E) {
    int i = blockIdx.x * blockDim.x + threadIdx.x;
    if (i < E) {
        int s = src[i];
        int pos = __ldg(&g_off[dst[i]]) + g_tick[i];
        g_csr2[pos] = make_int2(s, __float_as_int(__ldg(&g_dinv[s])));
    }
}

// ---------------- weight prep (merged) ---------------------------------------
__global__ void k_wprep(const float *__restrict__ W1, const float *__restrict__ W2) {
    int i = blockIdx.x * blockDim.x + threadIdx.x;
    if (i < HID * FIN) {
        int n = i >> 8, k = i & 255;
        float x = W1[(size_t)k * HID + n];
        __nv_bfloat16 h = __float2bfloat16(x);
        g_w1t_hi[i] = h;
        g_w1t_lo[i] = __float2bfloat16(x - __bfloat162float(h));
    } else if (i < HID * FIN + NCP * HID) {
        int q = i - HID * FIN;
        int n = q >> 7, k = q & 127;
        float x = (n < NC) ? W2[(size_t)k * NC + n] : 0.f;
        __nv_bfloat16 h = __float2bfloat16(x);
        g_w2t_hi[q] = h;
        g_w2t_lo[q] = __float2bfloat16(x - __bfloat162float(h));
    }
}

// ---------------- GEMM1: bf16-split 3-pass, 2 CTA/SM, cp.async B -----------
#define A_T 1280
#define B_T 2560
#define G1_SMEM ((4 * A_T + 4 * B_T) * 4)   // 61440 bytes

__global__ __launch_bounds__(256, 2) void k_gemm1_mma(const float *__restrict__ X) {
    extern __shared__ uint32_t sm[];
    uint32_t *aB = sm;
    uint32_t *bB = sm + 4 * A_T;

    const int tid  = threadIdx.x;
    const int wid  = tid >> 5, lane = tid & 31;
    const int g    = lane >> 2, tig = lane & 3;
    const int wM   = (wid & 1) * 32;
    const int wN   = (wid >> 1) * 32;
    const int m0   = blockIdx.x * 64;

    const uint32_t aAddr = smem_u32(aB);
    const uint32_t bAddr = smem_u32(bB);

    const int aRow = (lane & 15);
    const int aCol = (lane >> 4) * 4;
    const int bRow = ((lane & 16) ? 8 : 0) + (lane & 7);
    const int bCol = ((lane & 8) ? 4 : 0);

    float acc[2][4][4];
#pragma unroll
    for (int i = 0; i < 2; i++)
#pragma unroll
        for (int j = 0; j < 4; j++)
#pragma unroll
            for (int l = 0; l < 4; l++) acc[i][j][l] = 0.f;

    {
#pragma unroll
        for (int it = 0; it < 2; it++) {
            int q = tid + it * 256;
            int row = q >> 2, c4 = q & 3;
            uint32_t d = bAddr + (uint32_t)(row * 20 + c4 * 4) * 4;
            cp16(d, &g_w1t_hi[row * FIN + c4 * 8]);
            cp16(d + B_T * 4, &g_w1t_lo[row * FIN + c4 * 8]);
        }
        CP_COMMIT();
    }
    float4 stg[2];
#pragma unroll
    for (int it = 0; it < 2; it++) {
        int q = tid + it * 256;
        int row = q >> 3, c4 = q & 7;
        int grow = m0 + row;
        stg[it] = make_float4(0.f, 0.f, 0.f, 0.f);
        if (grow < NN)
            stg[it] = *reinterpret_cast<const float4 *>(&X[(size_t)grow * FIN + c4 * 4]);
    }
    {
        uint32_t *aHi = aB, *aLo = aB + A_T;
#pragma unroll
        for (int it = 0; it < 2; it++) {
            int q = tid + it * 256;
            int row = q >> 3, c4 = q & 7;
            float4 v = stg[it];
            float hx = __bfloat162float(__float2bfloat16(v.x));
            float hy = __bfloat162float(__float2bfloat16(v.y));
            float hz = __bfloat162float(__float2bfloat16(v.z));
            float hw = __bfloat162float(__float2bfloat16(v.w));
            int o = row * 20 + c4 * 2;
            aHi[o]     = bf16x2_of(hx, hy);
            aHi[o + 1] = bf16x2_of(hz, hw);
            aLo[o]     = bf16x2_of(v.x - hx, v.y - hy);
            aLo[o + 1] = bf16x2_of(v.z - hz, v.w - hw);
        }
    }
    CP_WAIT0();
    __syncthreads();

    for (int ch = 0; ch < 8; ch++) {
        const int nb = (ch + 1) & 1;
        if (ch < 7) {
#pragma unroll
            for (int it = 0; it < 2; it++) {
                int q = tid + it * 256;
                int row = q >> 2, c4 = q & 3;
                uint32_t d = bAddr + (uint32_t)(nb * 2 * B_T + row * 20 + c4 * 4) * 4;
                const int kbase = (ch + 1) * 32;
                cp16(d, &g_w1t_hi[row * FIN + kbase + c4 * 8]);
                cp16(d + B_T * 4, &g_w1t_lo[row * FIN + kbase + c4 * 8]);
            }
            CP_COMMIT();
#pragma unroll
            for (int it = 0; it < 2; it++) {
                int q = tid + it * 256;
                int row = q >> 3, c4 = q & 7;
                int grow = m0 + row;
                stg[it] = make_float4(0.f, 0.f, 0.f, 0.f);
                if (grow < NN)
                    stg[it] = *reinterpret_cast<const float4 *>(
                        &X[(size_t)grow * FIN + (ch + 1) * 32 + c4 * 4]);
            }
        }

        const uint32_t aHiAd = aAddr + (uint32_t)((ch & 1) * 2 * A_T) * 4;
        const uint32_t aLoAd = aHiAd + (uint32_t)A_T * 4;
        const uint32_t bHiAd = bAddr + (uint32_t)((ch & 1) * 2 * B_T) * 4;
        const uint32_t bLoAd = bHiAd + (uint32_t)B_T * 4;
#pragma unroll
        for (int k16 = 0; k16 < 2; k16++) {
            const int kw = k16 * 8;
            uint32_t Ah[2][4], Al[2][4], Bh[2][4], Bl[2][4];
#pragma unroll
            for (int ma = 0; ma < 2; ma++) {
                uint32_t off = (uint32_t)((wM + ma * 16 + aRow) * 20 + kw + aCol) * 4;
                ldm_x4(Ah[ma], aHiAd + off);
                ldm_x4(Al[ma], aLoAd + off);
            }
#pragma unroll
            for (int hf = 0; hf < 2; hf++) {
                uint32_t off = (uint32_t)((wN + hf * 16 + bRow) * 20 + kw + bCol) * 4;
                ldm_x4(Bh[hf], bHiAd + off);
                ldm_x4(Bl[hf], bLoAd + off);
            }
#pragma unroll
            for (int ma = 0; ma < 2; ma++)
#pragma unroll
                for (int na = 0; na < 4; na++)
                    mma_bf16(acc[ma][na], Ah[ma], &Bh[na >> 1][(na & 1) * 2]);
#pragma unroll
            for (int ma = 0; ma < 2; ma++)
#pragma unroll
                for (int na = 0; na < 4; na++)
                    mma_bf16(acc[ma][na], Ah[ma], &Bl[na >> 1][(na & 1) * 2]);
#pragma unroll
            for (int ma = 0; ma < 2; ma++)
#pragma unroll
                for (int na = 0; na < 4; na++)
                    mma_bf16(acc[ma][na], Al[ma], &Bh[na >> 1][(na & 1) * 2]);
        }

        if (ch < 7) {
            uint32_t *nHi = aB + nb * 2 * A_T;
            uint32_t *nLo = nHi + A_T;
#pragma unroll
            for (int it = 0; it < 2; it++) {
                int q = tid + it * 256;
                int row = q >> 3, c4 = q & 7;
                float4 v = stg[it];
                float hx = __bfloat162float(__float2bfloat16(v.x));
                float hy = __bfloat162float(__float2bfloat16(v.y));
                float hz = __bfloat162float(__float2bfloat16(v.z));
                float hw = __bfloat162float(__float2bfloat16(v.w));
                int o = row * 20 + c4 * 2;
                nHi[o]     = bf16x2_of(hx, hy);
                nHi[o + 1] = bf16x2_of(hz, hw);
                nLo[o]     = bf16x2_of(v.x - hx, v.y - hy);
                nLo[o + 1] = bf16x2_of(v.z - hz, v.w - hw);
            }
            CP_WAIT0();
            __syncthreads();
        }
    }

#pragma unroll
    for (int ma = 0; ma < 2; ma++) {
        int row0 = m0 + wM + ma * 16 + g;
        int row1 = row0 + 8;
#pragma unroll
        for (int na = 0; na < 4; na++) {
            int col = wN + na * 8 + tig * 2;
            if (row0 < NN)
                *reinterpret_cast<float2 *>(&g_xw[(size_t)row0 * HID + col]) =
                    make_float2(acc[ma][na][0], acc[ma][na][1]);
            if (row1 < NN)
                *reinterpret_cast<float2 *>(&g_xw[(size_t)row1 * HID + col]) =
                    make_float2(acc[ma][na][2], acc[ma][na][3]);
        }
    }
}

// ---------------- gather layer 1: warp/node, paired CSR ---------------------
__global__ __launch_bounds__(256) void k_gather1(const float *__restrict__ b1) {
    int w = (blockIdx.x * blockDim.x + threadIdx.x) >> 5;
    int lane = threadIdx.x & 31;
    if (w >= NN) return;
    float dw = g_dinv[w];
    int beg = g_off[w], n = g_cnt[w];      // beg is even

    float cs = dw * dw;
    float4 a0 = *reinterpret_cast<const float4 *>(&g_xw[(size_t)w * HID + lane * 4]);
    a0.x *= cs; a0.y *= cs; a0.z *= cs; a0.w *= cs;
    float4 a1 = make_float4(0.f, 0.f, 0.f, 0.f);

    int j = 0;
    for (; j + 2 <= n; j += 2) {
        int4 pp = *reinterpret_cast<const int4 *>(&g_csr2[beg + j]);   // 16B aligned
        int s0 = pp.x; float c0 = __int_as_float(pp.y) * dw;
        int s1 = pp.z; float c1 = __int_as_float(pp.w) * dw;
        float4 v0 = *reinterpret_cast<const float4 *>(&g_xw[(size_t)s0 * HID + lane * 4]);
        float4 v1 = *reinterpret_cast<const float4 *>(&g_xw[(size_t)s1 * HID + lane * 4]);
        a0.x = fmaf(v0.x, c0, a0.x); a0.y = fmaf(v0.y, c0, a0.y);
        a0.z = fmaf(v0.z, c0, a0.z); a0.w = fmaf(v0.w, c0, a0.w);
        a1.x = fmaf(v1.x, c1, a1.x); a1.y = fmaf(v1.y, c1, a1.y);
        a1.z = fmaf(v1.z, c1, a1.z); a1.w = fmaf(v1.w, c1, a1.w);
    }
    if (j < n) {
        int2 p = g_csr2[beg + j];
        int s0 = p.x; float c0 = __int_as_float(p.y) * dw;
        float4 v0 = *reinterpret_cast<const float4 *>(&g_xw[(size_t)s0 * HID + lane * 4]);
        a0.x = fmaf(v0.x, c0, a0.x); a0.y = fmaf(v0.y, c0, a0.y);
        a0.z = fmaf(v0.z, c0, a0.z); a0.w = fmaf(v0.w, c0, a0.w);
    }
    float4 b = reinterpret_cast<const float4 *>(b1)[lane];
    float4 r;
    r.x = fmaxf(a0.x + a1.x + b.x, 0.f);
    r.y = fmaxf(a0.y + a1.y + b.y, 0.f);
    r.z = fmaxf(a0.z + a1.z + b.z, 0.f);
    r.w = fmaxf(a0.w + a1.w + b.w, 0.f);

    float hx = __bfloat162float(__float2bfloat16(r.x));
    float hy = __bfloat162float(__float2bfloat16(r.y));
    float hz = __bfloat162float(__float2bfloat16(r.z));
    float hw = __bfloat162float(__float2bfloat16(r.w));
    uint2 hi = make_uint2(bf16x2_of(hx, hy), bf16x2_of(hz, hw));
    uint2 lo = make_uint2(bf16x2_of(r.x - hx, r.y - hy), bf16x2_of(r.z - hz, r.w - hw));
    size_t o = (size_t)w * HID + lane * 4;
    *reinterpret_cast<uint2 *>(&g_hhi[o]) = hi;
    *reinterpret_cast<uint2 *>(&g_hlo[o]) = lo;
}

// ---------------- GEMM2 via MMA: g_hw = h[NN,128] @ W2 (bf16 split) ---------
#define G2_AP 68
#define G2_AW (128 * G2_AP)
#define G2_BW (48 * G2_AP)
#define G2_SMEM ((2 * G2_AW + 2 * G2_BW) * 4)   // 95744 bytes

__global__ __launch_bounds__(256, 2) void k_gemm2_mma() {
    extern __shared__ uint32_t sm[];
    uint32_t *aHi = sm;
    uint32_t *aLo = sm + G2_AW;
    uint32_t *bHi = sm + 2 * G2_AW;
    uint32_t *bLo = sm + 2 * G2_AW + G2_BW;

    const int tid = threadIdx.x;
    const int wid = tid >> 5, lane = tid & 31;
    const int g   = lane >> 2, tig = lane & 3;
    const int wM  = (wid & 3) * 32;
    const int wN  = (wid >> 2) * 24;
    const int m0  = blockIdx.x * 128;

    const uint32_t aHiAd = smem_u32(aHi);
    const uint32_t aLoAd = smem_u32(aLo);
    const uint32_t bHiAd = smem_u32(bHi);
    const uint32_t bLoAd = smem_u32(bLo);

    const int aRow = (lane & 15);
    const int aCol = (lane >> 4) * 4;
    const int bRow = ((lane & 16) ? 8 : 0) + (lane & 7);
    const int bCol = ((lane & 8) ? 4 : 0);
    const int b2Row = (lane & 7);
    const int b2Col = ((lane & 8) ? 4 : 0);

#pragma unroll
    for (int it = 0; it < 8; it++) {
        int q = tid + it * 256;
        int row = q >> 4, c4 = q & 15;
        int grow = m0 + row;
        uint32_t d = (uint32_t)(row * G2_AP + c4 * 4) * 4;
        if (grow < NN) {
            size_t gi = (size_t)grow * HID + c4 * 8;
            cp16(aHiAd + d, &g_hhi[gi]);
            cp16(aLoAd + d, &g_hlo[gi]);
        } else {
            *reinterpret_cast<uint4 *>(&aHi[row * G2_AP + c4 * 4]) = make_uint4(0, 0, 0, 0);
            *reinterpret_cast<uint4 *>(&aLo[row * G2_AP + c4 * 4]) = make_uint4(0, 0, 0, 0);
        }
    }
#pragma unroll
    for (int it = 0; it < 3; it++) {
        int q = tid + it * 256;
        if (q < 48 * 16) {
            int row = q >> 4, c4 = q & 15;
            uint32_t d = (uint32_t)(row * G2_AP + c4 * 4) * 4;
            cp16(bHiAd + d, &g_w2t_hi[row * HID + c4 * 8]);
            cp16(bLoAd + d, &g_w2t_lo[row * HID + c4 * 8]);
        }
    }
    CP_COMMIT();
    CP_WAIT0();
    __syncthreads();

    float acc[2][3][4];
#pragma unroll
    for (int i = 0; i < 2; i++)
#pragma unroll
        for (int j = 0; j < 3; j++)
#pragma unroll
            for (int l = 0; l < 4; l++) acc[i][j][l] = 0.f;

#pragma unroll
    for (int k16 = 0; k16 < 8; k16++) {
        const int kw = k16 * 8;
        uint32_t Ah[2][4], Al[2][4], B4h[4], B4l[4], B2h[2], B2l[2];
#pragma unroll
        for (int ma = 0; ma < 2; ma++) {
            uint32_t off = (uint32_t)((wM + ma * 16 + aRow) * G2_AP + kw + aCol) * 4;
            ldm_x4(Ah[ma], aHiAd + off);
            ldm_x4(Al[ma], aLoAd + off);
        }
        {
            uint32_t off = (uint32_t)((wN + bRow) * G2_AP + kw + bCol) * 4;
            ldm_x4(B4h, bHiAd + off);
            ldm_x4(B4l, bLoAd + off);
            uint32_t off2 = (uint32_t)((wN + 16 + b2Row) * G2_AP + kw + b2Col) * 4;
            ldm_x2(B2h, bHiAd + off2);
            ldm_x2(B2l, bLoAd + off2);
        }
#pragma unroll
        for (int ma = 0; ma < 2; ma++) {
            mma_bf16(acc[ma][0], Ah[ma], &B4h[0]);
            mma_bf16(acc[ma][1], Ah[ma], &B4h[2]);
            mma_bf16(acc[ma][2], Ah[ma], B2h);
        }
#pragma unroll
        for (int ma = 0; ma < 2; ma++) {
            mma_bf16(acc[ma][0], Ah[ma], &B4l[0]);
            mma_bf16(acc[ma][1], Ah[ma], &B4l[2]);
            mma_bf16(acc[ma][2], Ah[ma], B2l);
        }
#pragma unroll
        for (int ma = 0; ma < 2; ma++) {
            mma_bf16(acc[ma][0], Al[ma], &B4h[0]);
            mma_bf16(acc[ma][1], Al[ma], &B4h[2]);
            mma_bf16(acc[ma][2], Al[ma], B2h);
        }
    }

#pragma unroll
    for (int ma = 0; ma < 2; ma++) {
        int row0 = m0 + wM + ma * 16 + g;
        int row1 = row0 + 8;
#pragma unroll
        for (int na = 0; na < 3; na++) {
            int col = wN + na * 8 + tig * 2;
            if (row0 < NN)
                *reinterpret_cast<float2 *>(&g_hw[(size_t)row0 * NCP + col]) =
                    make_float2(acc[ma][na][0], acc[ma][na][1]);
            if (row1 < NN)
                *reinterpret_cast<float2 *>(&g_hw[(size_t)row1 * NCP + col]) =
                    make_float2(acc[ma][na][2], acc[ma][na][3]);
        }
    }
}

// ---------------- gather layer 2 + bias + log_softmax -----------------------
__global__ __launch_bounds__(256) void k_gather2(const float *__restrict__ b2,
                                                 float *__restrict__ out) {
    int w = (blockIdx.x * blockDim.x + threadIdx.x) >> 5;
    int lane = threadIdx.x & 31;
    if (w >= NN) return;
    float dw = g_dinv[w];
    int beg = g_off[w], n = g_cnt[w];

    int grp = lane / 12;
    int col = lane - grp * 12;

    float4 acc = make_float4(0.f, 0.f, 0.f, 0.f);
    if (lane < 12) {
        float cs = dw * dw;
        float4 v = *reinterpret_cast<const float4 *>(&g_hw[(size_t)w * NCP + lane * 4]);
        acc = make_float4(v.x * cs, v.y * cs, v.z * cs, v.w * cs);
    }
    for (int j = 0; j < n; j += 2) {
        int e = j + grp;
        if (grp < 2 && e < n) {
            int2 p = g_csr2[beg + e];
            int s = p.x;
            float c = __int_as_float(p.y) * dw;
            float4 v = *reinterpret_cast<const float4 *>(&g_hw[(size_t)s * NCP + col * 4]);
            acc.x = fmaf(v.x, c, acc.x);
            acc.y = fmaf(v.y, c, acc.y);
            acc.z = fmaf(v.z, c, acc.z);
            acc.w = fmaf(v.w, c, acc.w);
        }
    }
    acc.x += __shfl_sync(0xffffffffu, acc.x, (lane + 12) & 31);
    acc.y += __shfl_sync(0xffffffffu, acc.y, (lane + 12) & 31);
    acc.z += __shfl_sync(0xffffffffu, acc.z, (lane + 12) & 31);
    acc.w += __shfl_sync(0xffffffffu, acc.w, (lane + 12) & 31);

    float zx = 0.f, zy = 0.f, zz = 0.f, zw = 0.f;
    bool act = (lane < 12);
    bool hasw = (lane < 11);
    if (act) {
        int c0 = lane * 4;
        zx = acc.x + b2[c0];
        zy = acc.y + b2[c0 + 1];
        zz = acc.z + b2[c0 + 2];
        zw = hasw ? (acc.w + b2[c0 + 3]) : -1e30f;
    }
    float m = act ? fmaxf(fmaxf(zx, zy), fmaxf(zz, zw)) : -1e30f;
#pragma unroll
    for (int o = 16; o > 0; o >>= 1)
        m = fmaxf(m, __shfl_xor_sync(0xffffffffu, m, o));
    float s = 0.f;
    if (act) s = expf(zx - m) + expf(zy - m) + expf(zz - m) + (hasw ? expf(zw - m) : 0.f);
#pragma unroll
    for (int o = 16; o > 0; o >>= 1)
        s += __shfl_xor_sync(0xffffffffu, s, o);
    float ls = logf(s) + m;
    if (act) {
        float *p = &out[(size_t)w * NC + lane * 4];
        p[0] = zx - ls;
        p[1] = zy - ls;
        p[2] = zz - ls;
        if (hasw) p[3] = zw - ls;
    }
}

// ---------------- launch: CSR chain forked onto side stream -----------------
extern "C" void kernel_launch(void *const *d_in, const int *in_sizes, int n_in,
                              void *d_out, int out_size) {
    const float *x  = (const float *)d_in[0];
    const int   *ei = (const int   *)d_in[1];
    const float *W1 = (const float *)d_in[2];
    const float *b1 = (const float *)d_in[3];
    const float *W2 = (const float *)d_in[4];
    const float *b2 = (const float *)d_in[5];
    float *out = (float *)d_out;

    const int E = in_sizes[1] / 2;
    const int *src = ei;
    const int *dst = ei + E;

    cudaFuncSetAttribute(k_gemm1_mma, cudaFuncAttributeMaxDynamicSharedMemorySize, G1_SMEM);
    cudaFuncSetAttribute(k_gemm2_mma, cudaFuncAttributeMaxDynamicSharedMemorySize, G2_SMEM);

    cudaEventRecord(g_evA, 0);
    cudaStreamWaitEvent(g_s1, g_evA, 0);

    k_zero_cnt<<<NB, 256, 0, g_s1>>>();
    k_hist<<<(E + 255) / 256, 256, 0, g_s1>>>(dst, E);
    k_scan_atomic<<<NB, 256, 0, g_s1>>>();
    k_fill<<<(E + 255) / 256, 256, 0, g_s1>>>(src, dst, E);
    cudaEventRecord(g_evB, g_s1);

    k_wprep<<<(HID * FIN + NCP * HID + 255) / 256, 256>>>(W1, W2);
    k_gemm1_mma<<<(NN + 63) / 64, 256, G1_SMEM>>>(x);

    cudaStreamWaitEvent(0, g_evB, 0);
    k_gather1<<<(NN * 32 + 255) / 256, 256>>>(b1);
    k_gemm2_mma<<<(NN + 127) / 128, 256, G2_SMEM>>>();
    k_gather2<<<(NN * 32 + 255) / 256, 256>>>(b2, out);
}

// round 17
// speedup vs baseline: 1.0895x; 1.0895x over previous
#include <cuda_runtime.h>
#include <cuda_bf16.h>
#include <cstdint>

#define NN   100000
#define FIN  256
#define HID  128
#define NC   47
#define NCP  48
#define EMAX 2000000
#define NB   ((NN + 255) / 256)
#define H0   50048                      // first-half nodes (= 391 gemm2 blocks)

// ---------------- scratch (device globals) ----------------------------------
__device__ float g_xw [(size_t)NN * HID];
__device__ __nv_bfloat16 g_hhi[(size_t)NN * HID];
__device__ __nv_bfloat16 g_hlo[(size_t)NN * HID];
__device__ float g_hw [(size_t)NN * NCP];
__device__ float g_dinv[NN];
__device__ int   g_cnt [NN];
__device__ int   g_off [NN];
__device__ int   g_tick[EMAX];
__device__ int   g_csr [EMAX];
__device__ int   g_total;
__device__ __nv_bfloat16 g_w1t_hi[HID * FIN];
__device__ __nv_bfloat16 g_w1t_lo[HID * FIN];
__device__ __nv_bfloat16 g_w2t_hi[NCP * HID];
__device__ __nv_bfloat16 g_w2t_lo[NCP * HID];

static cudaStream_t g_s1;
static cudaEvent_t  g_evA, g_evB, g_evC, g_evD;
static struct StreamInit {
    StreamInit() {
        cudaStreamCreateWithFlags(&g_s1, cudaStreamNonBlocking);
        cudaEventCreateWithFlags(&g_evA, cudaEventDisableTiming);
        cudaEventCreateWithFlags(&g_evB, cudaEventDisableTiming);
        cudaEventCreateWithFlags(&g_evC, cudaEventDisableTiming);
        cudaEventCreateWithFlags(&g_evD, cudaEventDisableTiming);
    }
} g_streamInit;

typedef unsigned long long ull;

__device__ __forceinline__ void mma_bf16(float *c, const uint32_t *a, const uint32_t *b) {
    asm("mma.sync.aligned.m16n8k16.row.col.f32.bf16.bf16.f32 "
        "{%0,%1,%2,%3}, {%4,%5,%6,%7}, {%8,%9}, {%0,%1,%2,%3};"
        : "+f"(c[0]), "+f"(c[1]), "+f"(c[2]), "+f"(c[3])
        : "r"(a[0]), "r"(a[1]), "r"(a[2]), "r"(a[3]), "r"(b[0]), "r"(b[1]));
}
__device__ __forceinline__ uint32_t bf16x2_of(float f0, float f1) {
    __nv_bfloat162 h = __floats2bfloat162_rn(f0, f1);
    return *reinterpret_cast<uint32_t *>(&h);
}
__device__ __forceinline__ uint32_t smem_u32(const void *p) {
    uint32_t a;
    asm("{ .reg .u64 t; cvta.to.shared.u64 t, %1; cvt.u32.u64 %0, t; }" : "=r"(a) : "l"(p));
    return a;
}
__device__ __forceinline__ void ldm_x4(uint32_t *r, uint32_t addr) {
    asm volatile("ldmatrix.sync.aligned.m8n8.x4.shared.b16 {%0,%1,%2,%3}, [%4];"
                 : "=r"(r[0]), "=r"(r[1]), "=r"(r[2]), "=r"(r[3]) : "r"(addr));
}
__device__ __forceinline__ void ldm_x2(uint32_t *r, uint32_t addr) {
    asm volatile("ldmatrix.sync.aligned.m8n8.x2.shared.b16 {%0,%1}, [%2];"
                 : "=r"(r[0]), "=r"(r[1]) : "r"(addr));
}
__device__ __forceinline__ void cp16(uint32_t dst, const void *src) {
    asm volatile("cp.async.ca.shared.global [%0], [%1], 16;" :: "r"(dst), "l"(src));
}
#define CP_COMMIT() asm volatile("cp.async.commit_group;")
#define CP_WAIT0()  asm volatile("cp.async.wait_group 0;" ::: "memory")

// ---------------- CSR build (ticket trick) -----------------------------------
__global__ void k_zero_cnt() {
    int i = blockIdx.x * blockDim.x + threadIdx.x;
    if (i < NN) g_cnt[i] = 0;
    if (blockIdx.x == 0 && threadIdx.x == 0) g_total = 0;
}
__global__ void k_hist(const int *__restrict__ dst, int E) {
    int i = blockIdx.x * blockDim.x + threadIdx.x;
    if (i < E) g_tick[i] = atomicAdd(&g_cnt[dst[i]], 1);
}
__global__ void k_scan_atomic() {
    __shared__ int sh[256];
    __shared__ int base;
    int t = threadIdx.x;
    int i = blockIdx.x * 256 + t;
    int v = (i < NN) ? g_cnt[i] : 0;
    sh[t] = v;
    __syncthreads();
#pragma unroll
    for (int o = 1; o < 256; o <<= 1) {
        int u = (t >= o) ? sh[t - o] : 0;
        __syncthreads();
        sh[t] += u;
        __syncthreads();
    }
    int incl = sh[t];
    if (t == 255) base = atomicAdd(&g_total, incl);
    __syncthreads();
    if (i < NN) {
        g_off[i] = base + incl - v;
        g_dinv[i] = rsqrtf((float)(v + 1));
    }
}
__global__ void k_fill(const int *__restrict__ src, const int *__restrict__ dst, int E) {
    int i = blockIdx.x * blockDim.x + threadIdx.x;
    if (i < E)
        g_csr[__ldg(&g_off[dst[i]]) + g_tick[i]] = src[i];
}

// ---------------- weight prep (merged) ---------------------------------------
__global__ void k_wprep(const float *__restrict__ W1, const float *__restrict__ W2) {
    int i = blockIdx.x * blockDim.x + threadIdx.x;
    if (i < HID * FIN) {
        int n = i >> 8, k = i & 255;
        float x = W1[(size_t)k * HID + n];
        __nv_bfloat16 h = __float2bfloat16(x);
        g_w1t_hi[i] = h;
        g_w1t_lo[i] = __float2bfloat16(x - __bfloat162float(h));
    } else if (i < HID * FIN + NCP * HID) {
        int q = i - HID * FIN;
        int n = q >> 7, k = q & 127;
        float x = (n < NC) ? W2[(size_t)k * NC + n] : 0.f;
        __nv_bfloat16 h = __float2bfloat16(x);
        g_w2t_hi[q] = h;
        g_w2t_lo[q] = __float2bfloat16(x - __bfloat162float(h));
    }
}

// ---------------- GEMM1: bf16-split 3-pass, 2 CTA/SM, cp.async B -----------
#define A_T 1280
#define B_T 2560
#define G1_SMEM ((4 * A_T + 4 * B_T) * 4)   // 61440 bytes

__global__ __launch_bounds__(256, 2) void k_gemm1_mma(const float *__restrict__ X) {
    extern __shared__ uint32_t sm[];
    uint32_t *aB = sm;
    uint32_t *bB = sm + 4 * A_T;

    const int tid  = threadIdx.x;
    const int wid  = tid >> 5, lane = tid & 31;
    const int g    = lane >> 2, tig = lane & 3;
    const int wM   = (wid & 1) * 32;
    const int wN   = (wid >> 1) * 32;
    const int m0   = blockIdx.x * 64;

    const uint32_t aAddr = smem_u32(aB);
    const uint32_t bAddr = smem_u32(bB);

    const int aRow = (lane & 15);
    const int aCol = (lane >> 4) * 4;
    const int bRow = ((lane & 16) ? 8 : 0) + (lane & 7);
    const int bCol = ((lane & 8) ? 4 : 0);

    float acc[2][4][4];
#pragma unroll
    for (int i = 0; i < 2; i++)
#pragma unroll
        for (int j = 0; j < 4; j++)
#pragma unroll
            for (int l = 0; l < 4; l++) acc[i][j][l] = 0.f;

    {
#pragma unroll
        for (int it = 0; it < 2; it++) {
            int q = tid + it * 256;
            int row = q >> 2, c4 = q & 3;
            uint32_t d = bAddr + (uint32_t)(row * 20 + c4 * 4) * 4;
            cp16(d, &g_w1t_hi[row * FIN + c4 * 8]);
            cp16(d + B_T * 4, &g_w1t_lo[row * FIN + c4 * 8]);
        }
        CP_COMMIT();
    }
    float4 stg[2];
#pragma unroll
    for (int it = 0; it < 2; it++) {
        int q = tid + it * 256;
        int row = q >> 3, c4 = q & 7;
        int grow = m0 + row;
        stg[it] = make_float4(0.f, 0.f, 0.f, 0.f);
        if (grow < NN)
            stg[it] = *reinterpret_cast<const float4 *>(&X[(size_t)grow * FIN + c4 * 4]);
    }
    {
        uint32_t *aHi = aB, *aLo = aB + A_T;
#pragma unroll
        for (int it = 0; it < 2; it++) {
            int q = tid + it * 256;
            int row = q >> 3, c4 = q & 7;
            float4 v = stg[it];
            float hx = __bfloat162float(__float2bfloat16(v.x));
            float hy = __bfloat162float(__float2bfloat16(v.y));
            float hz = __bfloat162float(__float2bfloat16(v.z));
            float hw = __bfloat162float(__float2bfloat16(v.w));
            int o = row * 20 + c4 * 2;
            aHi[o]     = bf16x2_of(hx, hy);
            aHi[o + 1] = bf16x2_of(hz, hw);
            aLo[o]     = bf16x2_of(v.x - hx, v.y - hy);
            aLo[o + 1] = bf16x2_of(v.z - hz, v.w - hw);
        }
    }
    CP_WAIT0();
    __syncthreads();

    for (int ch = 0; ch < 8; ch++) {
        const int nb = (ch + 1) & 1;
        if (ch < 7) {
#pragma unroll
            for (int it = 0; it < 2; it++) {
                int q = tid + it * 256;
                int row = q >> 2, c4 = q & 3;
                uint32_t d = bAddr + (uint32_t)(nb * 2 * B_T + row * 20 + c4 * 4) * 4;
                const int kbase = (ch + 1) * 32;
                cp16(d, &g_w1t_hi[row * FIN + kbase + c4 * 8]);
                cp16(d + B_T * 4, &g_w1t_lo[row * FIN + kbase + c4 * 8]);
            }
            CP_COMMIT();
#pragma unroll
            for (int it = 0; it < 2; it++) {
                int q = tid + it * 256;
                int row = q >> 3, c4 = q & 7;
                int grow = m0 + row;
                stg[it] = make_float4(0.f, 0.f, 0.f, 0.f);
                if (grow < NN)
                    stg[it] = *reinterpret_cast<const float4 *>(
                        &X[(size_t)grow * FIN + (ch + 1) * 32 + c4 * 4]);
            }
        }

        const uint32_t aHiAd = aAddr + (uint32_t)((ch & 1) * 2 * A_T) * 4;
        const uint32_t aLoAd = aHiAd + (uint32_t)A_T * 4;
        const uint32_t bHiAd = bAddr + (uint32_t)((ch & 1) * 2 * B_T) * 4;
        const uint32_t bLoAd = bHiAd + (uint32_t)B_T * 4;
#pragma unroll
        for (int k16 = 0; k16 < 2; k16++) {
            const int kw = k16 * 8;
            uint32_t Ah[2][4], Al[2][4], Bh[2][4], Bl[2][4];
#pragma unroll
            for (int ma = 0; ma < 2; ma++) {
                uint32_t off = (uint32_t)((wM + ma * 16 + aRow) * 20 + kw + aCol) * 4;
                ldm_x4(Ah[ma], aHiAd + off);
                ldm_x4(Al[ma], aLoAd + off);
            }
#pragma unroll
            for (int hf = 0; hf < 2; hf++) {
                uint32_t off = (uint32_t)((wN + hf * 16 + bRow) * 20 + kw + bCol) * 4;
                ldm_x4(Bh[hf], bHiAd + off);
                ldm_x4(Bl[hf], bLoAd + off);
            }
#pragma unroll
            for (int ma = 0; ma < 2; ma++)
#pragma unroll
                for (int na = 0; na < 4; na++)
                    mma_bf16(acc[ma][na], Ah[ma], &Bh[na >> 1][(na & 1) * 2]);
#pragma unroll
            for (int ma = 0; ma < 2; ma++)
#pragma unroll
                for (int na = 0; na < 4; na++)
                    mma_bf16(acc[ma][na], Ah[ma], &Bl[na >> 1][(na & 1) * 2]);
#pragma unroll
            for (int ma = 0; ma < 2; ma++)
#pragma unroll
                for (int na = 0; na < 4; na++)
                    mma_bf16(acc[ma][na], Al[ma], &Bh[na >> 1][(na & 1) * 2]);
        }

        if (ch < 7) {
            uint32_t *nHi = aB + nb * 2 * A_T;
            uint32_t *nLo = nHi + A_T;
#pragma unroll
            for (int it = 0; it < 2; it++) {
                int q = tid + it * 256;
                int row = q >> 3, c4 = q & 7;
                float4 v = stg[it];
                float hx = __bfloat162float(__float2bfloat16(v.x));
                float hy = __bfloat162float(__float2bfloat16(v.y));
                float hz = __bfloat162float(__float2bfloat16(v.z));
                float hw = __bfloat162float(__float2bfloat16(v.w));
                int o = row * 20 + c4 * 2;
                nHi[o]     = bf16x2_of(hx, hy);
                nHi[o + 1] = bf16x2_of(hz, hw);
                nLo[o]     = bf16x2_of(v.x - hx, v.y - hy);
                nLo[o + 1] = bf16x2_of(v.z - hz, v.w - hw);
            }
            CP_WAIT0();
            __syncthreads();
        }
    }

#pragma unroll
    for (int ma = 0; ma < 2; ma++) {
        int row0 = m0 + wM + ma * 16 + g;
        int row1 = row0 + 8;
#pragma unroll
        for (int na = 0; na < 4; na++) {
            int col = wN + na * 8 + tig * 2;
            if (row0 < NN)
                *reinterpret_cast<float2 *>(&g_xw[(size_t)row0 * HID + col]) =
                    make_float2(acc[ma][na][0], acc[ma][na][1]);
            if (row1 < NN)
                *reinterpret_cast<float2 *>(&g_xw[(size_t)row1 * HID + col]) =
                    make_float2(acc[ma][na][2], acc[ma][na][3]);
        }
    }
}

// ---------------- gather layer 1: warp/node (half-range) --------------------
__global__ __launch_bounds__(256) void k_gather1(const float *__restrict__ b1,
                                                 int nbase, int ncnt) {
    int w = nbase + ((blockIdx.x * blockDim.x + threadIdx.x) >> 5);
    int lane = threadIdx.x & 31;
    if (w >= nbase + ncnt) return;
    float dw = g_dinv[w];
    int beg = g_off[w], n = g_cnt[w];

    float cs = dw * dw;
    float4 a0 = *reinterpret_cast<const float4 *>(&g_xw[(size_t)w * HID + lane * 4]);
    a0.x *= cs; a0.y *= cs; a0.z *= cs; a0.w *= cs;
    float4 a1 = make_float4(0.f, 0.f, 0.f, 0.f);

    int j = 0;
    for (; j + 2 <= n; j += 2) {
        int s0 = __ldg(&g_csr[beg + j]);
        int s1 = __ldg(&g_csr[beg + j + 1]);
        float c0 = __ldg(&g_dinv[s0]) * dw;
        float c1 = __ldg(&g_dinv[s1]) * dw;
        float4 v0 = *reinterpret_cast<const float4 *>(&g_xw[(size_t)s0 * HID + lane * 4]);
        float4 v1 = *reinterpret_cast<const float4 *>(&g_xw[(size_t)s1 * HID + lane * 4]);
        a0.x = fmaf(v0.x, c0, a0.x); a0.y = fmaf(v0.y, c0, a0.y);
        a0.z = fmaf(v0.z, c0, a0.z); a0.w = fmaf(v0.w, c0, a0.w);
        a1.x = fmaf(v1.x, c1, a1.x); a1.y = fmaf(v1.y, c1, a1.y);
        a1.z = fmaf(v1.z, c1, a1.z); a1.w = fmaf(v1.w, c1, a1.w);
    }
    if (j < n) {
        int s0 = __ldg(&g_csr[beg + j]);
        float c0 = __ldg(&g_dinv[s0]) * dw;
        float4 v0 = *reinterpret_cast<const float4 *>(&g_xw[(size_t)s0 * HID + lane * 4]);
        a0.x = fmaf(v0.x, c0, a0.x); a0.y = fmaf(v0.y, c0, a0.y);
        a0.z = fmaf(v0.z, c0, a0.z); a0.w = fmaf(v0.w, c0, a0.w);
    }
    float4 b = reinterpret_cast<const float4 *>(b1)[lane];
    float4 r;
    r.x = fmaxf(a0.x + a1.x + b.x, 0.f);
    r.y = fmaxf(a0.y + a1.y + b.y, 0.f);
    r.z = fmaxf(a0.z + a1.z + b.z, 0.f);
    r.w = fmaxf(a0.w + a1.w + b.w, 0.f);

    float hx = __bfloat162float(__float2bfloat16(r.x));
    float hy = __bfloat162float(__float2bfloat16(r.y));
    float hz = __bfloat162float(__float2bfloat16(r.z));
    float hw = __bfloat162float(__float2bfloat16(r.w));
    uint2 hi = make_uint2(bf16x2_of(hx, hy), bf16x2_of(hz, hw));
    uint2 lo = make_uint2(bf16x2_of(r.x - hx, r.y - hy), bf16x2_of(r.z - hz, r.w - hw));
    size_t o = (size_t)w * HID + lane * 4;
    *reinterpret_cast<uint2 *>(&g_hhi[o]) = hi;
    *reinterpret_cast<uint2 *>(&g_hlo[o]) = lo;
}

// ---------------- GEMM2 via MMA (block-offset half) --------------------------
#define G2_AP 68
#define G2_AW (128 * G2_AP)
#define G2_BW (48 * G2_AP)
#define G2_SMEM ((2 * G2_AW + 2 * G2_BW) * 4)   // 95744 bytes

__global__ __launch_bounds__(256, 2) void k_gemm2_mma(int blkbase) {
    extern __shared__ uint32_t sm[];
    uint32_t *aHi = sm;
    uint32_t *aLo = sm + G2_AW;
    uint32_t *bHi = sm + 2 * G2_AW;
    uint32_t *bLo = sm + 2 * G2_AW + G2_BW;

    const int tid = threadIdx.x;
    const int wid = tid >> 5, lane = tid & 31;
    const int g   = lane >> 2, tig = lane & 3;
    const int wM  = (wid & 3) * 32;
    const int wN  = (wid >> 2) * 24;
    const int m0  = (blkbase + blockIdx.x) * 128;

    const uint32_t aHiAd = smem_u32(aHi);
    const uint32_t aLoAd = smem_u32(aLo);
    const uint32_t bHiAd = smem_u32(bHi);
    const uint32_t bLoAd = smem_u32(bLo);

    const int aRow = (lane & 15);
    const int aCol = (lane >> 4) * 4;
    const int bRow = ((lane & 16) ? 8 : 0) + (lane & 7);
    const int bCol = ((lane & 8) ? 4 : 0);
    const int b2Row = (lane & 7);
    const int b2Col = ((lane & 8) ? 4 : 0);

#pragma unroll
    for (int it = 0; it < 8; it++) {
        int q = tid + it * 256;
        int row = q >> 4, c4 = q & 15;
        int grow = m0 + row;
        uint32_t d = (uint32_t)(row * G2_AP + c4 * 4) * 4;
        if (grow < NN) {
            size_t gi = (size_t)grow * HID + c4 * 8;
            cp16(aHiAd + d, &g_hhi[gi]);
            cp16(aLoAd + d, &g_hlo[gi]);
        } else {
            *reinterpret_cast<uint4 *>(&aHi[row * G2_AP + c4 * 4]) = make_uint4(0, 0, 0, 0);
            *reinterpret_cast<uint4 *>(&aLo[row * G2_AP + c4 * 4]) = make_uint4(0, 0, 0, 0);
        }
    }
#pragma unroll
    for (int it = 0; it < 3; it++) {
        int q = tid + it * 256;
        if (q < 48 * 16) {
            int row = q >> 4, c4 = q & 15;
            uint32_t d = (uint32_t)(row * G2_AP + c4 * 4) * 4;
            cp16(bHiAd + d, &g_w2t_hi[row * HID + c4 * 8]);
            cp16(bLoAd + d, &g_w2t_lo[row * HID + c4 * 8]);
        }
    }
    CP_COMMIT();
    CP_WAIT0();
    __syncthreads();

    float acc[2][3][4];
#pragma unroll
    for (int i = 0; i < 2; i++)
#pragma unroll
        for (int j = 0; j < 3; j++)
#pragma unroll
            for (int l = 0; l < 4; l++) acc[i][j][l] = 0.f;

#pragma unroll
    for (int k16 = 0; k16 < 8; k16++) {
        const int kw = k16 * 8;
        uint32_t Ah[2][4], Al[2][4], B4h[4], B4l[4], B2h[2], B2l[2];
#pragma unroll
        for (int ma = 0; ma < 2; ma++) {
            uint32_t off = (uint32_t)((wM + ma * 16 + aRow) * G2_AP + kw + aCol) * 4;
            ldm_x4(Ah[ma], aHiAd + off);
            ldm_x4(Al[ma], aLoAd + off);
        }
        {
            uint32_t off = (uint32_t)((wN + bRow) * G2_AP + kw + bCol) * 4;
            ldm_x4(B4h, bHiAd + off);
            ldm_x4(B4l, bLoAd + off);
            uint32_t off2 = (uint32_t)((wN + 16 + b2Row) * G2_AP + kw + b2Col) * 4;
            ldm_x2(B2h, bHiAd + off2);
            ldm_x2(B2l, bLoAd + off2);
        }
#pragma unroll
        for (int ma = 0; ma < 2; ma++) {
            mma_bf16(acc[ma][0], Ah[ma], &B4h[0]);
            mma_bf16(acc[ma][1], Ah[ma], &B4h[2]);
            mma_bf16(acc[ma][2], Ah[ma], B2h);
        }
#pragma unroll
        for (int ma = 0; ma < 2; ma++) {
            mma_bf16(acc[ma][0], Ah[ma], &B4l[0]);
            mma_bf16(acc[ma][1], Ah[ma], &B4l[2]);
            mma_bf16(acc[ma][2], Ah[ma], B2l);
        }
#pragma unroll
        for (int ma = 0; ma < 2; ma++) {
            mma_bf16(acc[ma][0], Al[ma], &B4h[0]);
            mma_bf16(acc[ma][1], Al[ma], &B4h[2]);
            mma_bf16(acc[ma][2], Al[ma], B2h);
        }
    }

#pragma unroll
    for (int ma = 0; ma < 2; ma++) {
        int row0 = m0 + wM + ma * 16 + g;
        int row1 = row0 + 8;
#pragma unroll
        for (int na = 0; na < 3; na++) {
            int col = wN + na * 8 + tig * 2;
            if (row0 < NN)
                *reinterpret_cast<float2 *>(&g_hw[(size_t)row0 * NCP + col]) =
                    make_float2(acc[ma][na][0], acc[ma][na][1]);
            if (row1 < NN)
                *reinterpret_cast<float2 *>(&g_hw[(size_t)row1 * NCP + col]) =
                    make_float2(acc[ma][na][2], acc[ma][na][3]);
        }
    }
}

// ---------------- gather layer 2 + bias + log_softmax -----------------------
__global__ __launch_bounds__(256) void k_gather2(const float *__restrict__ b2,
                                                 float *__restrict__ out) {
    int w = (blockIdx.x * blockDim.x + threadIdx.x) >> 5;
    int lane = threadIdx.x & 31;
    if (w >= NN) return;
    float dw = g_dinv[w];
    int beg = g_off[w], n = g_cnt[w];

    int grp = lane / 12;
    int col = lane - grp * 12;

    float4 acc = make_float4(0.f, 0.f, 0.f, 0.f);
    if (lane < 12) {
        float cs = dw * dw;
        float4 v = *reinterpret_cast<const float4 *>(&g_hw[(size_t)w * NCP + lane * 4]);
        acc = make_float4(v.x * cs, v.y * cs, v.z * cs, v.w * cs);
    }
    for (int j = 0; j < n; j += 2) {
        int e = j + grp;
        if (grp < 2 && e < n) {
            int s = __ldg(&g_csr[beg + e]);
            float c = __ldg(&g_dinv[s]) * dw;
            float4 v = *reinterpret_cast<const float4 *>(&g_hw[(size_t)s * NCP + col * 4]);
            acc.x = fmaf(v.x, c, acc.x);
            acc.y = fmaf(v.y, c, acc.y);
            acc.z = fmaf(v.z, c, acc.z);
            acc.w = fmaf(v.w, c, acc.w);
        }
    }
    acc.x += __shfl_sync(0xffffffffu, acc.x, (lane + 12) & 31);
    acc.y += __shfl_sync(0xffffffffu, acc.y, (lane + 12) & 31);
    acc.z += __shfl_sync(0xffffffffu, acc.z, (lane + 12) & 31);
    acc.w += __shfl_sync(0xffffffffu, acc.w, (lane + 12) & 31);

    float zx = 0.f, zy = 0.f, zz = 0.f, zw = 0.f;
    bool act = (lane < 12);
    bool hasw = (lane < 11);
    if (act) {
        int c0 = lane * 4;
        zx = acc.x + b2[c0];
        zy = acc.y + b2[c0 + 1];
        zz = acc.z + b2[c0 + 2];
        zw = hasw ? (acc.w + b2[c0 + 3]) : -1e30f;
    }
    float m = act ? fmaxf(fmaxf(zx, zy), fmaxf(zz, zw)) : -1e30f;
#pragma unroll
    for (int o = 16; o > 0; o >>= 1)
        m = fmaxf(m, __shfl_xor_sync(0xffffffffu, m, o));
    float s = 0.f;
    if (act) s = expf(zx - m) + expf(zy - m) + expf(zz - m) + (hasw ? expf(zw - m) : 0.f);
#pragma unroll
    for (int o = 16; o > 0; o >>= 1)
        s += __shfl_xor_sync(0xffffffffu, s, o);
    float ls = logf(s) + m;
    if (act) {
        float *p = &out[(size_t)w * NC + lane * 4];
        p[0] = zx - ls;
        p[1] = zy - ls;
        p[2] = zz - ls;
        if (hasw) p[3] = zw - ls;
    }
}

// ---------------- launch: CSR on side stream + split tail pipeline ----------
extern "C" void kernel_launch(void *const *d_in, const int *in_sizes, int n_in,
                              void *d_out, int out_size) {
    const float *x  = (const float *)d_in[0];
    const int   *ei = (const int   *)d_in[1];
    const float *W1 = (const float *)d_in[2];
    const float *b1 = (const float *)d_in[3];
    const float *W2 = (const float *)d_in[4];
    const float *b2 = (const float *)d_in[5];
    float *out = (float *)d_out;

    const int E = in_sizes[1] / 2;
    const int *src = ei;
    const int *dst = ei + E;

    cudaFuncSetAttribute(k_gemm1_mma, cudaFuncAttributeMaxDynamicSharedMemorySize, G1_SMEM);
    cudaFuncSetAttribute(k_gemm2_mma, cudaFuncAttributeMaxDynamicSharedMemorySize, G2_SMEM);

    // fork: CSR chain on side stream
    cudaEventRecord(g_evA, 0);
    cudaStreamWaitEvent(g_s1, g_evA, 0);
    k_zero_cnt<<<NB, 256, 0, g_s1>>>();
    k_hist<<<(E + 255) / 256, 256, 0, g_s1>>>(dst, E);
    k_scan_atomic<<<NB, 256, 0, g_s1>>>();
    k_fill<<<(E + 255) / 256, 256, 0, g_s1>>>(src, dst, E);
    cudaEventRecord(g_evB, g_s1);

    // main: weight prep + gemm1
    k_wprep<<<(HID * FIN + NCP * HID + 255) / 256, 256>>>(W1, W2);
    k_gemm1_mma<<<(NN + 63) / 64, 256, G1_SMEM>>>(x);
    cudaEventRecord(g_evC, 0);

    // main: first half of layer-1 aggregation + gemm2
    cudaStreamWaitEvent(0, g_evB, 0);
    k_gather1<<<(H0 * 32 + 255) / 256, 256>>>(b1, 0, H0);
    k_gemm2_mma<<<H0 / 128, 256, G2_SMEM>>>(0);

    // side: second half (CSR already done on this stream; wait for gemm1)
    cudaStreamWaitEvent(g_s1, g_evC, 0);
    k_gather1<<<((NN - H0) * 32 + 255) / 256, 256, 0, g_s1>>>(b1, H0, NN - H0);
    k_gemm2_mma<<<(NN + 127) / 128 - H0 / 128, 256, G2_SMEM, g_s1>>>(H0 / 128);
    cudaEventRecord(g_evD, g_s1);

    // join: gather2 needs all of g_hw
    cudaStreamWaitEvent(0, g_evD, 0);
    k_gather2<<<(NN * 32 + 255) / 256, 256>>>(b2, out);
}